// round 4
// baseline (speedup 1.0000x reference)
#include <cuda_runtime.h>

#define TT 256

// Ping-pong scratch (static device arrays: no allocation anywhere).
__device__ float g_bufX[33554432];
__device__ float g_bufY[33554432];

__device__ __forceinline__ void ffma2(unsigned long long& acc,
                                      unsigned long long w,
                                      unsigned long long v) {
    asm("fma.rn.f32x2 %0, %1, %2, %3;" : "=l"(acc) : "l"(w), "l"(v), "l"(acc));
}

// ---------------------------------------------------------------------------
// Dynamics kernel: per-neuron sequential loop over T, software-pipelined
// register prefetch (double-buffered chunks) to hide DRAM latency.
// MODE 0: psp only
// MODE 1: spike + psp
// MODE 2: sumpool2 + spike + psp (4-tap gather fused)
// MODE 3: bilinear-up2 + spike + psp (4-tap gather fused)
// MODE 4: spike only
// ---------------------------------------------------------------------------
template<int MODE>
__global__ void dyn_kernel(const float* __restrict__ in, float* __restrict__ out,
                           int H, int W, int N)
{
    int n = blockIdx.x * blockDim.x + threadIdx.x;
    if (n >= N) return;

    const float dsr  = 0.9048374180359595f;   // exp(-1/10)
    const float psc  = 0.27182818284590452f;  // e/10
    const float dref = 0.36787944117144233f;  // exp(-1)

    constexpr int S  = (MODE == 2 || MODE == 3) ? 4 : 1;
    constexpr int CH = (S == 4) ? 8 : 16;     // timesteps per chunk
    constexpr int F4 = CH / 4;                // float4 per stream per chunk
    constexpr int NC = TT / CH;

    const float* p[S];
    float w00 = 0.f, w01 = 0.f, w10 = 0.f, w11 = 0.f;

    if (MODE == 2) {
        int x = n % W, y = (n / W) % H, bc = n / (W * H);
        int Win = 2 * W;
        const float* base = in + (((long)bc * (2 * H) + 2 * y) * Win + 2 * x) * TT;
        p[0] = base;
        p[1] = base + TT;
        p[2] = base + (long)Win * TT;
        p[3] = base + (long)(Win + 1) * TT;
    } else if (MODE == 3) {
        int x = n % W, y = (n / W) % H, bc = n / (W * H);
        int Hin = H / 2, Win = W / 2;
        int jy = y >> 1, jx = x >> 1;
        int ya, yb, xa, xb; float wya, wyb, wxa, wxb;
        if ((y & 1) == 0) { ya = (jy > 0) ? jy - 1 : 0; yb = jy; wya = 0.25f; wyb = 0.75f; }
        else              { ya = jy; yb = (jy + 1 < Hin) ? jy + 1 : Hin - 1; wya = 0.75f; wyb = 0.25f; }
        if ((x & 1) == 0) { xa = (jx > 0) ? jx - 1 : 0; xb = jx; wxa = 0.25f; wxb = 0.75f; }
        else              { xa = jx; xb = (jx + 1 < Win) ? jx + 1 : Win - 1; wxa = 0.75f; wxb = 0.25f; }
        const float* base = in + (long)bc * Hin * Win * TT;
        p[0] = base + ((long)ya * Win + xa) * TT; w00 = wya * wxa;
        p[1] = base + ((long)ya * Win + xb) * TT; w01 = wya * wxb;
        p[2] = base + ((long)yb * Win + xa) * TT; w10 = wyb * wxa;
        p[3] = base + ((long)yb * Win + xb) * TT; w11 = wyb * wxb;
    } else {
        p[0] = in + (long)n * TT;
    }

    float* ob = out + (long)n * TT;

    float4 buf[2][S][F4];
    // preload chunk 0
    #pragma unroll
    for (int s = 0; s < S; s++)
        #pragma unroll
        for (int f = 0; f < F4; f++)
            buf[0][s][f] = *(const float4*)(p[s] + f * 4);

    float g1 = 0.f, g2 = 0.f, r = 0.f;

    for (int c = 0; c < NC; c++) {
        int cur = c & 1, nxt = cur ^ 1;
        if (c + 1 < NC) {
            #pragma unroll
            for (int s = 0; s < S; s++)
                #pragma unroll
                for (int f = 0; f < F4; f++)
                    buf[nxt][s][f] = *(const float4*)(p[s] + (c + 1) * CH + f * 4);
        }
        #pragma unroll
        for (int f = 0; f < F4; f++) {
            float u[4];
            if (MODE == 2) {
                float4 a = buf[cur][0][f], b = buf[cur][1][f];
                float4 cc = buf[cur][2][f], d = buf[cur][3][f];
                u[0] = 2.75f * ((a.x + b.x) + (cc.x + d.x));
                u[1] = 2.75f * ((a.y + b.y) + (cc.y + d.y));
                u[2] = 2.75f * ((a.z + b.z) + (cc.z + d.z));
                u[3] = 2.75f * ((a.w + b.w) + (cc.w + d.w));
            } else if (MODE == 3) {
                float4 a = buf[cur][0][f], b = buf[cur][1][f];
                float4 cc = buf[cur][2][f], d = buf[cur][3][f];
                u[0] = w00 * a.x + w01 * b.x + w10 * cc.x + w11 * d.x;
                u[1] = w00 * a.y + w01 * b.y + w10 * cc.y + w11 * d.y;
                u[2] = w00 * a.z + w01 * b.z + w10 * cc.z + w11 * d.z;
                u[3] = w00 * a.w + w01 * b.w + w10 * cc.w + w11 * d.w;
            } else {
                float4 a = buf[cur][0][f];
                u[0] = a.x; u[1] = a.y; u[2] = a.z; u[3] = a.w;
            }
            float o[4];
            #pragma unroll
            for (int j = 0; j < 4; j++) {
                if (MODE == 0) {
                    g1 = fmaf(dsr, g1, u[j]);
                    g2 = fmaf(dsr, g2, g1);
                    o[j] = psc * (g2 - g1);
                } else {
                    float v = u[j] + r - 10.0f;
                    float s = (v >= 0.f) ? 1.f : 0.f;
                    r = dref * (r - 20.f * s);
                    if (MODE == 4) {
                        o[j] = s;
                    } else {
                        g1 = fmaf(dsr, g1, s);
                        g2 = fmaf(dsr, g2, g1);
                        o[j] = psc * (g2 - g1);
                    }
                }
            }
            *(float4*)(ob + c * CH + f * 4) = make_float4(o[0], o[1], o[2], o[3]);
        }
    }
}

// ---------------------------------------------------------------------------
// T-vectorized conv with packed fp32x2 FMA (SASS FFMA2).
// One output pixel per block, OCG output channels, 128 threads x 2 timesteps.
// Weights staged to smem pre-duplicated into both f32 halves of a u64 so the
// inner loop is: 1 LDG.64 (data pair) + LDS.128 broadcast (2 packed weights)
// + fma.rn.f32x2 per output channel.
// ---------------------------------------------------------------------------
template<int IC, int KS, int PAD, int OCG>
__global__ __launch_bounds__(128)
void conv_kernel(const float* __restrict__ in, const float* __restrict__ wgt,
                 float* __restrict__ out, int H, int W, int OC)
{
    __shared__ __align__(16) unsigned long long sw[IC * KS * KS * OCG];

    int pix = blockIdx.x;
    int x = pix % W, y = (pix / W) % H, b = pix / (W * H);
    int oc0 = blockIdx.y * OCG;

    for (int i = threadIdx.x; i < IC * KS * KS * OCG; i += 128) {
        int k = i / OCG, o = i % OCG;
        unsigned u = __float_as_uint(wgt[(long)(oc0 + o) * IC * KS * KS + k]);
        sw[i] = ((unsigned long long)u << 32) | u;
    }
    __syncthreads();

    int t = threadIdx.x * 2;
    unsigned long long acc[OCG];
    #pragma unroll
    for (int o = 0; o < OCG; o++) acc[o] = 0ull;

    const long planeT = (long)H * W * TT;
    const float* inb = in + (long)b * IC * planeT + t;

    #pragma unroll
    for (int kh = 0; kh < KS; kh++) {
        int yy = y + kh - PAD;
        if (yy < 0 || yy >= H) continue;
        #pragma unroll
        for (int kw = 0; kw < KS; kw++) {
            int xx = x + kw - PAD;
            if (xx < 0 || xx >= W) continue;
            const float* p = inb + ((long)yy * W + xx) * TT;
            int kidx = kh * KS + kw;
            #pragma unroll 4
            for (int ic = 0; ic < IC; ic++) {
                unsigned long long v = *(const unsigned long long*)(p + (long)ic * planeT);
                const unsigned long long* swp = &sw[(ic * KS * KS + kidx) * OCG];
                if constexpr (OCG % 2 == 0) {
                    #pragma unroll
                    for (int o = 0; o < OCG; o += 2) {
                        ulonglong2 wv = *(const ulonglong2*)(swp + o);
                        ffma2(acc[o    ], wv.x, v);
                        ffma2(acc[o + 1], wv.y, v);
                    }
                } else {
                    #pragma unroll
                    for (int o = 0; o < OCG; o++)
                        ffma2(acc[o], swp[o], v);
                }
            }
        }
    }

    float* ob = out + ((long)b * OC + oc0) * planeT + ((long)y * W + x) * TT + t;
    #pragma unroll
    for (int o = 0; o < OCG; o++)
        *(unsigned long long*)(ob + (long)o * planeT) = acc[o];
}

// ---------------------------------------------------------------------------
// 15 launches, ping-pong X<->Y:
//   P0=psp(in); A1=conv1(P0); P1=sp(A1); P2=pool_sp(P1); A3=conv2(P2);
//   P3=sp(A3); P4=pool_sp(P3); A5=conv3(P4); P5=sp(A5); P6=up_sp(P5);
//   A7=conv4(P6); P7=sp(A7); P8=up_sp(P7); A9=conv_out(P8); out=spike(A9)
// ---------------------------------------------------------------------------
extern "C" void kernel_launch(void* const* d_in, const int* in_sizes, int n_in,
                              void* d_out, int out_size)
{
    const float* inp = (const float*)d_in[0];  // [4,1,32,32,256]
    const float* w1  = (const float*)d_in[1];  // [16,1,5,5,1]
    const float* w2  = (const float*)d_in[2];  // [32,16,3,3,1]
    const float* w3  = (const float*)d_in[3];  // [64,32,3,3,1]
    const float* w4  = (const float*)d_in[4];  // [32,64,3,3,1]
    const float* wo  = (const float*)d_in[5];  // [1,32,1,1,1]
    float* out = (float*)d_out;

    float *X, *Y;
    cudaGetSymbolAddress((void**)&X, g_bufX);
    cudaGetSymbolAddress((void**)&Y, g_bufY);

    // dyn launcher: small grids get small blocks to cover more SMs
    #define DYN(MODE, IN, OUT, H, W, N) do {                                  \
        int tpb_ = ((N) <= 8192) ? 64 : 128;                                  \
        dyn_kernel<MODE><<<((N) + tpb_ - 1) / tpb_, tpb_>>>(IN, OUT, H, W, N);\
    } while (0)

    // L1: psp(input) -> X ; conv1 -> Y ; spike+psp -> X
    DYN(0, inp, X, 32, 32, 4096);
    conv_kernel<1, 5, 2, 16><<<dim3(4096, 1), 128>>>(X, w1, Y, 32, 32, 16);
    DYN(1, Y, X, 32, 32, 65536);

    // L2: pool + spike + psp -> Y   (P2: [4,16,16,16])
    DYN(2, X, Y, 16, 16, 16384);

    // L3: conv2 -> X ; spike+psp -> Y
    conv_kernel<16, 3, 1, 16><<<dim3(1024, 2), 128>>>(Y, w2, X, 16, 16, 32);
    DYN(1, X, Y, 16, 16, 32768);

    // L4: pool + spike + psp -> X   (P4: [4,32,8,8])
    DYN(2, Y, X, 8, 8, 8192);

    // L5: conv3 -> Y ; spike+psp -> X
    conv_kernel<32, 3, 1, 16><<<dim3(256, 4), 128>>>(X, w3, Y, 8, 8, 64);
    DYN(1, Y, X, 8, 8, 16384);

    // L6: upsample + spike + psp -> Y   (P6: [4,64,16,16])
    DYN(3, X, Y, 16, 16, 65536);

    // L7: conv4 -> X ; spike+psp -> Y   (OCG=8: 36KB smem, 4096 blocks)
    conv_kernel<64, 3, 1, 8><<<dim3(1024, 4), 128>>>(Y, w4, X, 16, 16, 32);
    DYN(1, X, Y, 16, 16, 32768);

    // L8: upsample + spike + psp -> X   (P8: [4,32,32,32])
    DYN(3, Y, X, 32, 32, 131072);

    // L9: 1x1 conv -> Y ; spike only -> d_out
    conv_kernel<32, 1, 0, 1><<<dim3(4096, 1), 128>>>(X, wo, Y, 32, 32, 1);
    DYN(4, Y, out, 32, 32, 4096);

    #undef DYN
}

// round 5
// speedup vs baseline: 1.0660x; 1.0660x over previous
#include <cuda_runtime.h>

#define TT 256

// Ping-pong scratch (static device arrays: no allocation anywhere).
__device__ float g_bufX[33554432];
__device__ float g_bufY[33554432];

__device__ __forceinline__ void ffma2(unsigned long long& acc,
                                      unsigned long long w,
                                      unsigned long long v) {
    asm("fma.rn.f32x2 %0, %1, %2, %0;" : "+l"(acc) : "l"(w), "l"(v));
}

// ---------------------------------------------------------------------------
// Standalone dynamics kernel (only for input-psp, pool, upsample layers).
// MODE 0: psp only
// MODE 2: sumpool2 + spike + psp (4-tap gather fused)
// MODE 3: bilinear-up2 + spike + psp (4-tap gather fused)
// Software-pipelined register prefetch (double-buffered chunks).
// ---------------------------------------------------------------------------
template<int MODE>
__global__ void dyn_kernel(const float* __restrict__ in, float* __restrict__ out,
                           int H, int W, int N)
{
    int n = blockIdx.x * blockDim.x + threadIdx.x;
    if (n >= N) return;

    const float dsr  = 0.9048374180359595f;   // exp(-1/10)
    const float psc  = 0.27182818284590452f;  // e/10
    const float dref = 0.36787944117144233f;  // exp(-1)

    constexpr int S  = (MODE == 2 || MODE == 3) ? 4 : 1;
    constexpr int CH = (S == 4) ? 8 : 16;
    constexpr int F4 = CH / 4;
    constexpr int NC = TT / CH;

    const float* p[S];
    float w00 = 0.f, w01 = 0.f, w10 = 0.f, w11 = 0.f;

    if (MODE == 2) {
        int x = n % W, y = (n / W) % H, bc = n / (W * H);
        int Win = 2 * W;
        const float* base = in + (((long)bc * (2 * H) + 2 * y) * Win + 2 * x) * TT;
        p[0] = base;
        p[1] = base + TT;
        p[2] = base + (long)Win * TT;
        p[3] = base + (long)(Win + 1) * TT;
    } else if (MODE == 3) {
        int x = n % W, y = (n / W) % H, bc = n / (W * H);
        int Hin = H / 2, Win = W / 2;
        int jy = y >> 1, jx = x >> 1;
        int ya, yb, xa, xb; float wya, wyb, wxa, wxb;
        if ((y & 1) == 0) { ya = (jy > 0) ? jy - 1 : 0; yb = jy; wya = 0.25f; wyb = 0.75f; }
        else              { ya = jy; yb = (jy + 1 < Hin) ? jy + 1 : Hin - 1; wya = 0.75f; wyb = 0.25f; }
        if ((x & 1) == 0) { xa = (jx > 0) ? jx - 1 : 0; xb = jx; wxa = 0.25f; wxb = 0.75f; }
        else              { xa = jx; xb = (jx + 1 < Win) ? jx + 1 : Win - 1; wxa = 0.75f; wxb = 0.25f; }
        const float* base = in + (long)bc * Hin * Win * TT;
        p[0] = base + ((long)ya * Win + xa) * TT; w00 = wya * wxa;
        p[1] = base + ((long)ya * Win + xb) * TT; w01 = wya * wxb;
        p[2] = base + ((long)yb * Win + xa) * TT; w10 = wyb * wxa;
        p[3] = base + ((long)yb * Win + xb) * TT; w11 = wyb * wxb;
    } else {
        p[0] = in + (long)n * TT;
    }

    float* ob = out + (long)n * TT;

    float4 buf[2][S][F4];
    #pragma unroll
    for (int s = 0; s < S; s++)
        #pragma unroll
        for (int f = 0; f < F4; f++)
            buf[0][s][f] = *(const float4*)(p[s] + f * 4);

    float g1 = 0.f, g2 = 0.f, r = 0.f;

    for (int c = 0; c < NC; c++) {
        int cur = c & 1, nxt = cur ^ 1;
        if (c + 1 < NC) {
            #pragma unroll
            for (int s = 0; s < S; s++)
                #pragma unroll
                for (int f = 0; f < F4; f++)
                    buf[nxt][s][f] = *(const float4*)(p[s] + (c + 1) * CH + f * 4);
        }
        #pragma unroll
        for (int f = 0; f < F4; f++) {
            float u[4];
            if (MODE == 2) {
                float4 a = buf[cur][0][f], b = buf[cur][1][f];
                float4 cc = buf[cur][2][f], d = buf[cur][3][f];
                u[0] = 2.75f * ((a.x + b.x) + (cc.x + d.x));
                u[1] = 2.75f * ((a.y + b.y) + (cc.y + d.y));
                u[2] = 2.75f * ((a.z + b.z) + (cc.z + d.z));
                u[3] = 2.75f * ((a.w + b.w) + (cc.w + d.w));
            } else if (MODE == 3) {
                float4 a = buf[cur][0][f], b = buf[cur][1][f];
                float4 cc = buf[cur][2][f], d = buf[cur][3][f];
                u[0] = w00 * a.x + w01 * b.x + w10 * cc.x + w11 * d.x;
                u[1] = w00 * a.y + w01 * b.y + w10 * cc.y + w11 * d.y;
                u[2] = w00 * a.z + w01 * b.z + w10 * cc.z + w11 * d.z;
                u[3] = w00 * a.w + w01 * b.w + w10 * cc.w + w11 * d.w;
            } else {
                float4 a = buf[cur][0][f];
                u[0] = a.x; u[1] = a.y; u[2] = a.z; u[3] = a.w;
            }
            float o[4];
            #pragma unroll
            for (int j = 0; j < 4; j++) {
                if (MODE == 0) {
                    g1 = fmaf(dsr, g1, u[j]);
                    g2 = fmaf(dsr, g2, g1);
                    o[j] = psc * (g2 - g1);
                } else {
                    float v = u[j] + r - 10.0f;
                    float s = (v >= 0.f) ? 1.f : 0.f;
                    r = dref * (r - 20.f * s);
                    g1 = fmaf(dsr, g1, s);
                    g2 = fmaf(dsr, g2, g1);
                    o[j] = psc * (g2 - g1);
                }
            }
            *(float4*)(ob + c * CH + f * 4) = make_float4(o[0], o[1], o[2], o[3]);
        }
    }
}

// ---------------------------------------------------------------------------
// Fused conv + spike/psp epilogue.
// One output pixel per block, OCG output channels, 128 threads x 2 timesteps,
// packed fp32x2 FMA (tied "+l" operand -> clean FFMA2, no MOV churn).
// After the conv, accumulators are staged in smem; OCG threads run the
// 256-step spike(+psp) recurrence in place; all threads store the next
// layer's PSP tensor coalesced. The raw conv activation never hits GMEM.
// EPI = 1: spike + psp.  EPI = 4: spike only (final layer).
// ---------------------------------------------------------------------------
template<int IC, int KS, int PAD, int OCG, int EPI>
__global__ __launch_bounds__(128)
void conv_kernel(const float* __restrict__ in, const float* __restrict__ wgt,
                 float* __restrict__ out, int H, int W, int OC)
{
    __shared__ __align__(16) unsigned long long sw[IC * KS * KS * OCG];
    __shared__ __align__(16) float sa[OCG][260];

    int pix = blockIdx.x;
    int x = pix % W, y = (pix / W) % H, b = pix / (W * H);
    int oc0 = blockIdx.y * OCG;

    for (int i = threadIdx.x; i < IC * KS * KS * OCG; i += 128) {
        int k = i / OCG, o = i % OCG;
        unsigned u = __float_as_uint(wgt[(long)(oc0 + o) * IC * KS * KS + k]);
        sw[i] = ((unsigned long long)u << 32) | u;
    }
    __syncthreads();

    int t = threadIdx.x * 2;
    unsigned long long acc[OCG];
    #pragma unroll
    for (int o = 0; o < OCG; o++) acc[o] = 0ull;

    const long planeT = (long)H * W * TT;
    const float* inb = in + (long)b * IC * planeT + t;

    #pragma unroll
    for (int kh = 0; kh < KS; kh++) {
        int yy = y + kh - PAD;
        if (yy < 0 || yy >= H) continue;
        #pragma unroll
        for (int kw = 0; kw < KS; kw++) {
            int xx = x + kw - PAD;
            if (xx < 0 || xx >= W) continue;
            const float* p = inb + ((long)yy * W + xx) * TT;
            int kidx = kh * KS + kw;
            #pragma unroll 4
            for (int ic = 0; ic < IC; ic++) {
                unsigned long long v = *(const unsigned long long*)(p + (long)ic * planeT);
                const unsigned long long* swp = &sw[(ic * KS * KS + kidx) * OCG];
                if constexpr (OCG % 2 == 0) {
                    #pragma unroll
                    for (int o = 0; o < OCG; o += 2) {
                        ulonglong2 wv = *(const ulonglong2*)(swp + o);
                        ffma2(acc[o    ], wv.x, v);
                        ffma2(acc[o + 1], wv.y, v);
                    }
                } else {
                    #pragma unroll
                    for (int o = 0; o < OCG; o++)
                        ffma2(acc[o], swp[o], v);
                }
            }
        }
    }

    // Stage conv results: sa[oc][t] (pad 260 avoids systematic conflicts).
    #pragma unroll
    for (int o = 0; o < OCG; o++)
        *(float2*)&sa[o][t] = *(float2*)&acc[o];
    __syncthreads();

    // Per-channel serial recurrence over T (OCG threads; hidden under the
    // conv work of co-resident blocks).
    if (threadIdx.x < OCG) {
        const float dsr  = 0.9048374180359595f;
        const float psc  = 0.27182818284590452f;
        const float dref = 0.36787944117144233f;
        int oc = threadIdx.x;
        float g1 = 0.f, g2 = 0.f, r = 0.f;
        float4 nxt = *(float4*)&sa[oc][0];
        for (int tt = 0; tt < TT; tt += 4) {
            float4 a = nxt;
            if (tt + 4 < TT) nxt = *(float4*)&sa[oc][tt + 4];
            float u[4] = {a.x, a.y, a.z, a.w};
            float o4[4];
            #pragma unroll
            for (int j = 0; j < 4; j++) {
                float v = u[j] + r - 10.0f;
                float s = (v >= 0.f) ? 1.f : 0.f;
                r = dref * (r - 20.f * s);
                if (EPI == 4) {
                    o4[j] = s;
                } else {
                    g1 = fmaf(dsr, g1, s);
                    g2 = fmaf(dsr, g2, g1);
                    o4[j] = psc * (g2 - g1);
                }
            }
            *(float4*)&sa[oc][tt] = make_float4(o4[0], o4[1], o4[2], o4[3]);
        }
    }
    __syncthreads();

    // Coalesced store of the PSP (or spike) tensor.
    float* ob = out + ((long)b * OC + oc0) * planeT + ((long)y * W + x) * TT + t;
    #pragma unroll
    for (int o = 0; o < OCG; o++)
        *(float2*)(ob + (long)o * planeT) = *(float2*)&sa[o][t];
}

// ---------------------------------------------------------------------------
// 10 launches, ping-pong X<->Y:
//   P0=psp(in)->X; P1=conv1+sp(X)->Y; P2=pool_sp(Y)->X; P3=conv2+sp(X)->Y;
//   P4=pool_sp(Y)->X; P5=conv3+sp(X)->Y; P6=up_sp(Y)->X; P7=conv4+sp(X)->Y;
//   P8=up_sp(Y)->X; out=conv_out+spike(X)
// ---------------------------------------------------------------------------
extern "C" void kernel_launch(void* const* d_in, const int* in_sizes, int n_in,
                              void* d_out, int out_size)
{
    const float* inp = (const float*)d_in[0];  // [4,1,32,32,256]
    const float* w1  = (const float*)d_in[1];  // [16,1,5,5,1]
    const float* w2  = (const float*)d_in[2];  // [32,16,3,3,1]
    const float* w3  = (const float*)d_in[3];  // [64,32,3,3,1]
    const float* w4  = (const float*)d_in[4];  // [32,64,3,3,1]
    const float* wo  = (const float*)d_in[5];  // [1,32,1,1,1]
    float* out = (float*)d_out;

    float *X, *Y;
    cudaGetSymbolAddress((void**)&X, g_bufX);
    cudaGetSymbolAddress((void**)&Y, g_bufY);

    // P0 = psp(input) -> X        (N=4096: 32-thread blocks -> 128 blocks)
    dyn_kernel<0><<<128, 32>>>(inp, X, 32, 32, 4096);

    // P1 = spike/psp(conv1(P0)) -> Y
    conv_kernel<1, 5, 2, 16, 1><<<dim3(4096, 1), 128>>>(X, w1, Y, 32, 32, 16);

    // P2 = pool+spike+psp(P1) -> X   [4,16,16,16]  (N=16384: 256 blocks)
    dyn_kernel<2><<<256, 64>>>(Y, X, 16, 16, 16384);

    // P3 = spike/psp(conv2(P2)) -> Y
    conv_kernel<16, 3, 1, 16, 1><<<dim3(1024, 2), 128>>>(X, w2, Y, 16, 16, 32);

    // P4 = pool+spike+psp(P3) -> X   [4,32,8,8]  (N=8192: 256 blocks)
    dyn_kernel<2><<<256, 32>>>(Y, X, 8, 8, 8192);

    // P5 = spike/psp(conv3(P4)) -> Y
    conv_kernel<32, 3, 1, 16, 1><<<dim3(256, 4), 128>>>(X, w3, Y, 8, 8, 64);

    // P6 = up+spike+psp(P5) -> X   [4,64,16,16]  (N=65536)
    dyn_kernel<3><<<512, 128>>>(Y, X, 16, 16, 65536);

    // P7 = spike/psp(conv4(P6)) -> Y   (OCG=8 keeps smem under 48KB)
    conv_kernel<64, 3, 1, 8, 1><<<dim3(1024, 4), 128>>>(X, w4, Y, 16, 16, 32);

    // P8 = up+spike+psp(P7) -> X   [4,32,32,32]  (N=131072)
    dyn_kernel<3><<<1024, 128>>>(Y, X, 32, 32, 131072);

    // out = spike(conv_out(P8))
    conv_kernel<32, 1, 0, 1, 4><<<dim3(4096, 1), 128>>>(X, wo, out, 32, 32, 1);
}